// round 14
// baseline (speedup 1.0000x reference)
#include <cuda_runtime.h>

// ChamferLoss: B=8, N=M=8192, D=3 fp32, inputs ~ N(0,1).
// out = mean_n min_m ||gt_n - pred_m||^2 + mean_m min_n ||pred_m - gt_n||^2
//
// Grid-accelerated exact NN. R13 model: k_query (~125us) is ISSUE-bound on
// candidate evaluation (~25M pairs x ~8.5 instr). Two changes:
//  - G 32->48: candidates scale with h^3 -> ~10M pairs. Setup arrays slimmed:
//    counts go directly into a +1-shifted offs array (in-place scan); the
//    scatter atomicAdd leaves exactly the inclusive-end array queries need.
//  - candidates stored as {x,y,z,b2}; query evaluates t = b2 - 2q.b with
//    3 FFMA + 1 FMNMX + 1 LDG (q2 = q.w added once at the end, then clamp).
// Exact min (ring bound unchanged); deterministic fixed-order reduction.

#define BATCH   8
#define NPTS    8192
#define G       48
#define CELLS   (G * G * G)            // 110592
#define NROWS   (G * G)                // 2304 uint64 bitmask words per sb
#define NSB     (2 * BATCH)            // (side,batch); side 0=gts 1=preds
#define RANGE   6.0f                   // grid covers [-6,6]^3; max|coord|~4.7
#define HCELL   (2.0f * RANGE / G)     // 0.25
#define INVH    ((float)G / (2.0f * RANGE))
#define NTOT    (NSB * NPTS)           // 131072
#define SEG     (CELLS / 1024)         // 108 cells per scan thread
#define FINF    3.402823466e+38f

__device__ int                g_offs [NSB * (CELLS + 1)];  // +1-shifted
__device__ unsigned long long g_bits [NSB * NROWS];
__device__ float4             g_sorted[NSB * NPTS];        // {x,y,z,b2}
__device__ int                g_sidx  [NSB * NPTS];        // original indices
__device__ float              g_minbuf[NSB * NPTS];        // min d2 by orig idx
__device__ float              g_blocksums[512];

__device__ __forceinline__ void cell_of(float x, float y, float z,
                                        int& cx, int& cy, int& cz) {
    cx = min(G - 1, max(0, (int)floorf((x + RANGE) * INVH)));
    cy = min(G - 1, max(0, (int)floorf((y + RANGE) * INVH)));
    cz = min(G - 1, max(0, (int)floorf((z + RANGE) * INVH)));
}

__device__ __forceinline__ unsigned long long range_mask64(int lo, int hi) {
    // bits lo..hi inclusive, 0 <= lo <= hi <= 62 here (G-1 = 47)
    return ((1ull << (hi + 1)) - 1ull) & ~((1ull << lo) - 1ull);
}

// 1. zero offs + bitmask
__global__ __launch_bounds__(256)
void k_zero() {
    int i = blockIdx.x * 256 + threadIdx.x;
    const int NOFF = NSB * (CELLS + 1);
    for (int k = i; k < NOFF; k += gridDim.x * 256) g_offs[k] = 0;
    for (int k = i; k < NSB * NROWS; k += gridDim.x * 256) g_bits[k] = 0ull;
}

// 2. count points per cell (into offs[c+1]) + mark nonempty rows
__global__ __launch_bounds__(256)
void k_count(const float* __restrict__ gts, const float* __restrict__ preds) {
    int idx = blockIdx.x * 256 + threadIdx.x;
    int sb  = idx >> 13;
    int i   = idx & (NPTS - 1);
    int side = sb >> 3, b = sb & 7;
    const float* p = (side == 0 ? gts : preds) + ((size_t)b * NPTS + i) * 3;
    int cx, cy, cz;
    cell_of(p[0], p[1], p[2], cx, cy, cz);
    int c = (cz * G + cy) * G + cx;
    atomicAdd(&g_offs[sb * (CELLS + 1) + c + 1], 1);
    atomicOr(&g_bits[sb * NROWS + (cz * G + cy)], 1ull << cx);
}

// 3. in-place exclusive scan of positions 1..CELLS per sb (16 blocks x 1024)
__global__ __launch_bounds__(1024)
void k_scan() {
    const int sb = blockIdx.x;
    const int t  = threadIdx.x;
    int* Q = g_offs + sb * (CELLS + 1);
    const int base = 1 + t * SEG;

    int s = 0;
    for (int k = 0; k < SEG; ++k) s += Q[base + k];

    __shared__ int ws[32];
    int lane = t & 31, wid = t >> 5;
    int v = s;
#pragma unroll
    for (int d = 1; d < 32; d <<= 1) {
        int n = __shfl_up_sync(0xFFFFFFFFu, v, d);
        if (lane >= d) v += n;
    }
    if (lane == 31) ws[wid] = v;
    __syncthreads();
    if (wid == 0) {
        int w = ws[lane];
#pragma unroll
        for (int d = 1; d < 32; d <<= 1) {
            int n = __shfl_up_sync(0xFFFFFFFFu, w, d);
            if (lane >= d) w += n;
        }
        ws[lane] = w;
    }
    __syncthreads();
    int run = v - s + (wid ? ws[wid - 1] : 0);

    for (int k = 0; k < SEG; ++k) {
        int tmp = Q[base + k];
        Q[base + k] = run;      // exclusive start of cell (base+k-1)
        run += tmp;
    }
}

// 4. scatter: atomicAdd on offs[c+1] turns it into the inclusive end of c.
//    Query range of cell c afterwards: [offs[c], offs[c+1]).
__global__ __launch_bounds__(256)
void k_scatter(const float* __restrict__ gts, const float* __restrict__ preds) {
    int idx = blockIdx.x * 256 + threadIdx.x;
    int sb  = idx >> 13;
    int i   = idx & (NPTS - 1);
    int side = sb >> 3, b = sb & 7;
    const float* p = (side == 0 ? gts : preds) + ((size_t)b * NPTS + i) * 3;
    float x = p[0], y = p[1], z = p[2];
    int cx, cy, cz;
    cell_of(x, y, z, cx, cy, cz);
    int c   = (cz * G + cy) * G + cx;
    int pos = atomicAdd(&g_offs[sb * (CELLS + 1) + c + 1], 1);
    float b2 = x * x + y * y + z * z;
    g_sorted[sb * NPTS + pos] = make_float4(x, y, z, b2);
    g_sidx  [sb * NPTS + pos] = i;
}

// 5. exact NN query. Candidate eval: t = b2 - 2 q.b (3 FFMA + 1 min + 1 LDG);
//    d2 = q2 + t_min, clamped at write. Bitmask-pruned rows; two-phase.
__global__ __launch_bounds__(256)
void k_query() {
    __shared__ unsigned long long sbits[NROWS];

    int idx  = blockIdx.x * 256 + threadIdx.x;
    int qsb  = idx >> 13;
    int slot = idx & (NPTS - 1);
    int gsb  = qsb ^ 8;

    for (int k = threadIdx.x; k < NROWS; k += 256)
        sbits[k] = g_bits[gsb * NROWS + k];
    __syncthreads();

    float4 q = g_sorted[qsb * NPTS + slot];      // q.w = |q|^2
    const float mqx = -2.0f * q.x;
    const float mqy = -2.0f * q.y;
    const float mqz = -2.0f * q.z;
    int cx, cy, cz;
    cell_of(q.x, q.y, q.z, cx, cy, cz);

    const int*    offs = g_offs + gsb * (CELLS + 1);
    const float4* pts  = g_sorted + (size_t)gsb * NPTS;

    // ---- Phase 1: 3x3x3 neighborhood. Masks first, then all run bounds
    // (MLP), then the candidate loops. Border clamps duplicate rows; min is
    // idempotent so that's harmless.
    int xlo = max(cx - 1, 0), xhi = min(cx + 1, G - 1);
    unsigned long long xm = range_mask64(xlo, xhi);
    int ss[9], ee[9];
#pragma unroll
    for (int dz = 0; dz < 3; ++dz) {
        int z = min(max(cz + dz - 1, 0), G - 1);
#pragma unroll
        for (int dy = 0; dy < 3; ++dy) {
            int y   = min(max(cy + dy - 1, 0), G - 1);
            int row = z * G + y;
            unsigned long long m = sbits[row] & xm;
            int k = dz * 3 + dy;
            if (m) {
                int x0 = __ffsll(m) - 1;
                int x1 = 63 - __clzll(m);
                ss[k] = offs[row * G + x0];
                ee[k] = offs[row * G + x1 + 1];
            } else {
                ss[k] = 0; ee[k] = 0;
            }
        }
    }

    float best = FINF;   // min over t = b2 - 2 q.b
#pragma unroll
    for (int k = 0; k < 9; ++k) {
        int s = ss[k], e = ee[k];
        for (; s + 4 <= e; s += 4) {
            float4 p0 = pts[s + 0];
            float4 p1 = pts[s + 1];
            float4 p2 = pts[s + 2];
            float4 p3 = pts[s + 3];
            float t0 = fmaf(mqz, p0.z, fmaf(mqy, p0.y, fmaf(mqx, p0.x, p0.w)));
            float t1 = fmaf(mqz, p1.z, fmaf(mqy, p1.y, fmaf(mqx, p1.x, p1.w)));
            float t2 = fmaf(mqz, p2.z, fmaf(mqy, p2.y, fmaf(mqx, p2.x, p2.w)));
            float t3 = fmaf(mqz, p3.z, fmaf(mqy, p3.y, fmaf(mqx, p3.x, p3.w)));
            best = fminf(best, fminf(fminf(t0, t1), fminf(t2, t3)));
        }
        for (; s < e; ++s) {
            float4 p = pts[s];
            best = fminf(best,
                fmaf(mqz, p.z, fmaf(mqy, p.y, fmaf(mqx, p.x, p.w))));
        }
    }

    // ---- Phase 2: rare tail. After ring r, unscanned points are >= r*HCELL
    // away; d2 = q.w + best. Bitmask row tests from shared, offs only for
    // set bits.
    if (q.w + best > HCELL * HCELL) {
        for (int r = 2; r <= G; ++r) {
            int zlo = max(cz - r, 0), zhi = min(cz + r, G - 1);
            for (int z = zlo; z <= zhi; ++z) {
                int adz = abs(z - cz);
                int ylo = max(cy - r, 0), yhi = min(cy + r, G - 1);
                for (int y = ylo; y <= yhi; ++y) {
                    int ady = abs(y - cy);
                    int row = z * G + y;
                    unsigned long long m;
                    if (adz == r || ady == r) {
                        m = sbits[row] &
                            range_mask64(max(cx - r, 0), min(cx + r, G - 1));
                    } else {
                        unsigned long long em = 0ull;
                        if (cx - r >= 0) em |= 1ull << (cx - r);
                        if (cx + r < G)  em |= 1ull << (cx + r);
                        m = sbits[row] & em;
                    }
                    while (m) {
                        int x = __ffsll(m) - 1;
                        m &= m - 1ull;
                        int c  = row * G + x;
                        int s0 = offs[c], s1 = offs[c + 1];
                        for (int s = s0; s < s1; ++s) {
                            float4 p = pts[s];
                            best = fminf(best,
                                fmaf(mqz, p.z,
                                fmaf(mqy, p.y, fmaf(mqx, p.x, p.w))));
                        }
                    }
                }
            }
            float rb = (float)r * HCELL;
            if (q.w + best <= rb * rb) break;
        }
    }

    float v = fmaxf(q.w + best, 0.0f);   // d2, clamped (matches reference)
    g_minbuf[qsb * NPTS + g_sidx[qsb * NPTS + slot]] = v;
}

// 6. deterministic block-tree partial sums (fixed index order)
__global__ __launch_bounds__(256)
void k_reduce() {
    __shared__ float red[256];
    int i = blockIdx.x * 256 + threadIdx.x;
    red[threadIdx.x] = g_minbuf[i];
    __syncthreads();
#pragma unroll
    for (int s = 128; s > 0; s >>= 1) {
        if (threadIdx.x < s) red[threadIdx.x] += red[threadIdx.x + s];
        __syncthreads();
    }
    if (threadIdx.x == 0) g_blocksums[blockIdx.x] = red[0];
}

// 7. final: sum 512 partials; both means share denominator BATCH*NPTS
__global__ void k_final(float* __restrict__ out) {
    __shared__ float red[512];
    red[threadIdx.x] = g_blocksums[threadIdx.x];
    __syncthreads();
#pragma unroll
    for (int s = 256; s > 0; s >>= 1) {
        if (threadIdx.x < s) red[threadIdx.x] += red[threadIdx.x + s];
        __syncthreads();
    }
    if (threadIdx.x == 0)
        out[0] = red[0] / (float)(BATCH * NPTS);
}

extern "C" void kernel_launch(void* const* d_in, const int* in_sizes, int n_in,
                              void* d_out, int out_size) {
    const float* gts   = (const float*)d_in[0];
    const float* preds = (const float*)d_in[1];
    (void)in_sizes; (void)n_in; (void)out_size;

    k_zero<<<512, 256>>>();
    k_count<<<NTOT / 256, 256>>>(gts, preds);
    k_scan<<<NSB, 1024>>>();
    k_scatter<<<NTOT / 256, 256>>>(gts, preds);
    k_query<<<NTOT / 256, 256>>>();
    k_reduce<<<NTOT / 256, 256>>>();
    k_final<<<1, 512>>>((float*)d_out);
}

// round 15
// speedup vs baseline: 1.5328x; 1.5328x over previous
#include <cuda_runtime.h>

// ChamferLoss: B=8, N=M=8192, D=3 fp32, inputs ~ N(0,1).
// out = mean_n min_m ||gt_n - pred_m||^2 + mean_m min_n ||pred_m - gt_n||^2
//
// Grid-accelerated exact NN, G=32 (R13's G=48 blew up the phase-2 tail;
// reverted). Kept from R13: {x,y,z,b2} candidate form (t = b2 - 2 q.b,
// 1 LDG + 3 FFMA + 1 FMNMX per candidate) and the slim in-place offs build.
// NEW (R14): exact lower-bound pruning in phase 1 — scan the center row
// first, then visit the other 8 rows of the 3x3x3 neighborhood only if
// lb(row)^2 < best_d2, and within a surviving row keep side cells only if
// lb(row)^2 + lbx(cell)^2 < best_d2. Pruned cells provably cannot improve
// the min -> still exact. Deterministic fixed-order reduction unchanged.

#define BATCH   8
#define NPTS    8192
#define G       32
#define CELLS   (G * G * G)            // 32768
#define NROWS   (G * G)                // 1024 uint32 mask words per sb
#define NSB     (2 * BATCH)
#define RANGE   6.0f
#define HCELL   (2.0f * RANGE / G)     // 0.375
#define INVH    ((float)G / (2.0f * RANGE))
#define NTOT    (NSB * NPTS)           // 131072
#define SEG     (CELLS / 1024)         // 32
#define FINF    3.402823466e+38f

__device__ int      g_offs [NSB * (CELLS + 1)];  // +1-shifted counts -> ends
__device__ unsigned g_bits [NSB * NROWS];
__device__ float4   g_sorted[NSB * NPTS];        // {x,y,z,b2}
__device__ int      g_sidx  [NSB * NPTS];        // original indices
__device__ float    g_minbuf[NSB * NPTS];        // min d2 by orig idx
__device__ float    g_blocksums[512];

__device__ __forceinline__ void cell_of(float x, float y, float z,
                                        int& cx, int& cy, int& cz) {
    cx = min(G - 1, max(0, (int)floorf((x + RANGE) * INVH)));
    cy = min(G - 1, max(0, (int)floorf((y + RANGE) * INVH)));
    cz = min(G - 1, max(0, (int)floorf((z + RANGE) * INVH)));
}

__device__ __forceinline__ unsigned range_mask(int lo, int hi) {
    unsigned m = (hi >= 31) ? 0xFFFFFFFFu : ((1u << (hi + 1)) - 1u);
    return m & ~((1u << lo) - 1u);
}

// 1. zero offs + bitmask
__global__ __launch_bounds__(256)
void k_zero() {
    int i = blockIdx.x * 256 + threadIdx.x;
    const int NOFF = NSB * (CELLS + 1);
    for (int k = i; k < NOFF; k += gridDim.x * 256) g_offs[k] = 0;
    for (int k = i; k < NSB * NROWS; k += gridDim.x * 256) g_bits[k] = 0u;
}

// 2. count into offs[c+1] + mark nonempty rows
__global__ __launch_bounds__(256)
void k_count(const float* __restrict__ gts, const float* __restrict__ preds) {
    int idx = blockIdx.x * 256 + threadIdx.x;
    int sb  = idx >> 13;
    int i   = idx & (NPTS - 1);
    int side = sb >> 3, b = sb & 7;
    const float* p = (side == 0 ? gts : preds) + ((size_t)b * NPTS + i) * 3;
    int cx, cy, cz;
    cell_of(p[0], p[1], p[2], cx, cy, cz);
    int c = (cz * G + cy) * G + cx;
    atomicAdd(&g_offs[sb * (CELLS + 1) + c + 1], 1);
    atomicOr(&g_bits[sb * NROWS + (cz * G + cy)], 1u << cx);
}

// 3. in-place exclusive scan of positions 1..CELLS per sb (16 x 1024)
__global__ __launch_bounds__(1024)
void k_scan() {
    const int sb = blockIdx.x;
    const int t  = threadIdx.x;
    int* Q = g_offs + sb * (CELLS + 1);
    const int base = 1 + t * SEG;

    int s = 0;
#pragma unroll
    for (int k = 0; k < SEG; ++k) s += Q[base + k];

    __shared__ int ws[32];
    int lane = t & 31, wid = t >> 5;
    int v = s;
#pragma unroll
    for (int d = 1; d < 32; d <<= 1) {
        int n = __shfl_up_sync(0xFFFFFFFFu, v, d);
        if (lane >= d) v += n;
    }
    if (lane == 31) ws[wid] = v;
    __syncthreads();
    if (wid == 0) {
        int w = ws[lane];
#pragma unroll
        for (int d = 1; d < 32; d <<= 1) {
            int n = __shfl_up_sync(0xFFFFFFFFu, w, d);
            if (lane >= d) w += n;
        }
        ws[lane] = w;
    }
    __syncthreads();
    int run = v - s + (wid ? ws[wid - 1] : 0);

#pragma unroll
    for (int k = 0; k < SEG; ++k) {
        int tmp = Q[base + k];
        Q[base + k] = run;
        run += tmp;
    }
}

// 4. scatter; atomicAdd on offs[c+1] leaves inclusive end of cell c
__global__ __launch_bounds__(256)
void k_scatter(const float* __restrict__ gts, const float* __restrict__ preds) {
    int idx = blockIdx.x * 256 + threadIdx.x;
    int sb  = idx >> 13;
    int i   = idx & (NPTS - 1);
    int side = sb >> 3, b = sb & 7;
    const float* p = (side == 0 ? gts : preds) + ((size_t)b * NPTS + i) * 3;
    float x = p[0], y = p[1], z = p[2];
    int cx, cy, cz;
    cell_of(x, y, z, cx, cy, cz);
    int c   = (cz * G + cy) * G + cx;
    int pos = atomicAdd(&g_offs[sb * (CELLS + 1) + c + 1], 1);
    g_sorted[sb * NPTS + pos] = make_float4(x, y, z, x * x + y * y + z * z);
    g_sidx  [sb * NPTS + pos] = i;
}

// 5. exact NN query with lower-bound pruning
__global__ __launch_bounds__(256)
void k_query() {
    __shared__ unsigned sbits[NROWS];

    int idx  = blockIdx.x * 256 + threadIdx.x;
    int qsb  = idx >> 13;
    int slot = idx & (NPTS - 1);
    int gsb  = qsb ^ 8;

#pragma unroll
    for (int k = 0; k < NROWS / 256; ++k)
        sbits[threadIdx.x + k * 256] = g_bits[gsb * NROWS + threadIdx.x + k * 256];
    __syncthreads();

    float4 q = g_sorted[qsb * NPTS + slot];      // q.w = |q|^2
    const float mqx = -2.0f * q.x;
    const float mqy = -2.0f * q.y;
    const float mqz = -2.0f * q.z;
    int cx, cy, cz;
    cell_of(q.x, q.y, q.z, cx, cy, cz);

    // fractional position inside the home cell, distances to cell walls
    float fx = (q.x + RANGE) * INVH - (float)cx;
    float fy = (q.y + RANGE) * INVH - (float)cy;
    float fz = (q.z + RANGE) * INVH - (float)cz;
    float dxm = fx * HCELL, dxp = (1.0f - fx) * HCELL;   // to x- / x+ wall
    float dym = fy * HCELL, dyp = (1.0f - fy) * HCELL;
    float dzm = fz * HCELL, dzp = (1.0f - fz) * HCELL;

    const int*    offs = g_offs + gsb * (CELLS + 1);
    const float4* pts  = g_sorted + (size_t)gsb * NPTS;

    float best = FINF;   // min over t = b2 - 2 q.b ; d2 = q.w + best

#define SCAN_RUN(S, E)                                                       \
    {                                                                        \
        int s_ = (S), e_ = (E);                                              \
        for (; s_ + 4 <= e_; s_ += 4) {                                      \
            float4 p0 = pts[s_ + 0];                                         \
            float4 p1 = pts[s_ + 1];                                         \
            float4 p2 = pts[s_ + 2];                                         \
            float4 p3 = pts[s_ + 3];                                         \
            float t0 = fmaf(mqz, p0.z, fmaf(mqy, p0.y, fmaf(mqx, p0.x, p0.w))); \
            float t1 = fmaf(mqz, p1.z, fmaf(mqy, p1.y, fmaf(mqx, p1.x, p1.w))); \
            float t2 = fmaf(mqz, p2.z, fmaf(mqy, p2.y, fmaf(mqx, p2.x, p2.w))); \
            float t3 = fmaf(mqz, p3.z, fmaf(mqy, p3.y, fmaf(mqx, p3.x, p3.w))); \
            best = fminf(best, fminf(fminf(t0, t1), fminf(t2, t3)));         \
        }                                                                    \
        for (; s_ < e_; ++s_) {                                              \
            float4 p = pts[s_];                                              \
            best = fminf(best,                                               \
                fmaf(mqz, p.z, fmaf(mqy, p.y, fmaf(mqx, p.x, p.w))));        \
        }                                                                    \
    }

    // ---- Phase 1a: center row (dy=dz=0), full 3-cell run (mask-tightened).
    {
        int row = cz * G + cy;
        unsigned m = sbits[row] & range_mask(max(cx - 1, 0), min(cx + 1, G - 1));
        if (m) {
            int x0 = __ffs(m) - 1;
            int x1 = 31 - __clz(m);
            SCAN_RUN(offs[row * G + x0], offs[row * G + x1 + 1]);
        }
    }

    // ---- Phase 1b: remaining 8 rows with exact lower-bound pruning.
    // Order: 4 face rows first (tighter best earlier), then 4 corners.
    {
        const signed char RY[8] = {-1,  1,  0,  0, -1, -1,  1,  1};
        const signed char RZ[8] = { 0,  0, -1,  1, -1,  1, -1,  1};
#pragma unroll
        for (int k = 0; k < 8; ++k) {
            int dy = RY[k], dz = RZ[k];
            int y = cy + dy, z = cz + dz;
            if ((unsigned)y >= G || (unsigned)z >= G) continue;
            float lby = (dy > 0) ? dyp : ((dy < 0) ? dym : 0.0f);
            float lbz = (dz > 0) ? dzp : ((dz < 0) ? dzm : 0.0f);
            float lb2 = lby * lby + lbz * lbz;
            float bd2 = q.w + best;            // current best d2
            if (lb2 >= bd2) continue;

            // per-cell x pruning: side cells need lb2 + lbx^2 < bd2
            unsigned xm = 1u << cx;
            if (cx - 1 >= 0 && lb2 + dxm * dxm < bd2) xm |= 1u << (cx - 1);
            if (cx + 1 <  G && lb2 + dxp * dxp < bd2) xm |= 1u << (cx + 1);
            unsigned m = sbits[z * G + y] & xm;
            if (!m) continue;
            int x0 = __ffs(m) - 1;
            int x1 = 31 - __clz(m);
            int rowb = (z * G + y) * G;
            SCAN_RUN(offs[rowb + x0], offs[rowb + x1 + 1]);
        }
    }

    // ---- Phase 2: rare tail. Points outside the 3x3x3 neighborhood are
    // >= HCELL away; after finishing ring r everything unscanned is
    // >= r*HCELL away -> exact termination.
    if (q.w + best > HCELL * HCELL) {
        for (int r = 2; r <= G; ++r) {
            int zlo = max(cz - r, 0), zhi = min(cz + r, G - 1);
            for (int z = zlo; z <= zhi; ++z) {
                int adz = abs(z - cz);
                int ylo = max(cy - r, 0), yhi = min(cy + r, G - 1);
                for (int y = ylo; y <= yhi; ++y) {
                    int ady = abs(y - cy);
                    int row = z * G + y;
                    unsigned m;
                    if (adz == r || ady == r) {
                        m = sbits[row] &
                            range_mask(max(cx - r, 0), min(cx + r, G - 1));
                    } else {
                        unsigned em = 0;
                        if (cx - r >= 0) em |= 1u << (cx - r);
                        if (cx + r < G)  em |= 1u << (cx + r);
                        m = sbits[row] & em;
                    }
                    while (m) {
                        int x = __ffs(m) - 1;
                        m &= m - 1;
                        int c = row * G + x;
                        SCAN_RUN(offs[c], offs[c + 1]);
                    }
                }
            }
            float rb = (float)r * HCELL;
            if (q.w + best <= rb * rb) break;
        }
    }
#undef SCAN_RUN

    float v = fmaxf(q.w + best, 0.0f);   // d2 clamped (matches reference)
    g_minbuf[qsb * NPTS + g_sidx[qsb * NPTS + slot]] = v;
}

// 6. deterministic block-tree partial sums (fixed index order)
__global__ __launch_bounds__(256)
void k_reduce() {
    __shared__ float red[256];
    int i = blockIdx.x * 256 + threadIdx.x;
    red[threadIdx.x] = g_minbuf[i];
    __syncthreads();
#pragma unroll
    for (int s = 128; s > 0; s >>= 1) {
        if (threadIdx.x < s) red[threadIdx.x] += red[threadIdx.x + s];
        __syncthreads();
    }
    if (threadIdx.x == 0) g_blocksums[blockIdx.x] = red[0];
}

// 7. final: sum 512 partials; shared denominator BATCH*NPTS
__global__ void k_final(float* __restrict__ out) {
    __shared__ float red[512];
    red[threadIdx.x] = g_blocksums[threadIdx.x];
    __syncthreads();
#pragma unroll
    for (int s = 256; s > 0; s >>= 1) {
        if (threadIdx.x < s) red[threadIdx.x] += red[threadIdx.x + s];
        __syncthreads();
    }
    if (threadIdx.x == 0)
        out[0] = red[0] / (float)(BATCH * NPTS);
}

extern "C" void kernel_launch(void* const* d_in, const int* in_sizes, int n_in,
                              void* d_out, int out_size) {
    const float* gts   = (const float*)d_in[0];
    const float* preds = (const float*)d_in[1];
    (void)in_sizes; (void)n_in; (void)out_size;

    k_zero<<<512, 256>>>();
    k_count<<<NTOT / 256, 256>>>(gts, preds);
    k_scan<<<NSB, 1024>>>();
    k_scatter<<<NTOT / 256, 256>>>(gts, preds);
    k_query<<<NTOT / 256, 256>>>();
    k_reduce<<<NTOT / 256, 256>>>();
    k_final<<<1, 512>>>((float*)d_out);
}